// round 10
// baseline (speedup 1.0000x reference)
#include <cuda_runtime.h>
#include <cuda_bf16.h>
#include <cstdint>

// ---------------- problem constants ----------------
static constexpr int Bb  = 16;
static constexpr int Mm  = 1024;
static constexpr int Nn  = 4096;
static constexpr int CIN = 67;
static constexpr int HID = 128;
static constexpr int KS  = 384;          // split-bf16 concat K: [hi|lo|hi] x [hi|hi|lo]
static constexpr int QB  = 4;            // batches per overlap quarter

// ---------------- scratch (device globals; no cudaMalloc allowed) ----------------
__device__ __align__(128) __nv_bfloat16 g_A[(size_t)Bb * Mm * KS];   // 12.6 MB
__device__ __align__(128) __nv_bfloat16 g_Bm[(size_t)Bb * Nn * KS]; // 50 MB
__device__ float g_partial[Mm / 16][Bb * Nn];                        // colsum partials (16MB)
__device__ float g_rcolsum[Bb * Nn];                                 // reciprocal col L1 sums

__device__ __forceinline__ uint32_t smem_to_u32(const void* p) {
    uint32_t a;
    asm("{ .reg .u64 t; cvta.to.shared.u64 t, %1; cvt.u32.u64 %0, t; }" : "=r"(a) : "l"(p));
    return a;
}

// ================= K1: q/k projection + BN + bf16 split =================
__global__ void __launch_bounds__(128) qk_kernel(
    const float* __restrict__ cent, const float* __restrict__ feat,
    const float* __restrict__ Wq, const float* __restrict__ Wk,
    const float* __restrict__ gq, const float* __restrict__ bq,
    const float* __restrict__ mq, const float* __restrict__ vq,
    const float* __restrict__ gk, const float* __restrict__ bk,
    const float* __restrict__ mk, const float* __restrict__ vk)
{
    __shared__ float sW[HID * CIN];
    __shared__ float sin[CIN];
    const int ROWS = 64;
    long row0 = (long)blockIdx.x * ROWS;
    bool isQ = row0 < (long)Bb * Mm;
    const float* W = isQ ? Wq : Wk;
    for (int i = threadIdx.x; i < HID * CIN; i += blockDim.x) sW[i] = W[i];

    int h = threadIdx.x;
    float g_ = isQ ? gq[h] : gk[h];
    float b_ = isQ ? bq[h] : bk[h];
    float m_ = isQ ? mq[h] : mk[h];
    float v_ = isQ ? vq[h] : vk[h];
    float scale = g_ / sqrtf(v_ + 1e-5f);
    float shift = b_ - m_ * scale;

    const float* X = isQ ? cent : feat;
    long rbase = isQ ? row0 : row0 - (long)Bb * Mm;
    __nv_bfloat16* dst = isQ ? g_A : g_Bm;
    __syncthreads();

    for (int r = 0; r < ROWS; r++) {
        long row = rbase + r;
        if (threadIdx.x < CIN) sin[threadIdx.x] = X[row * CIN + threadIdx.x];
        __syncthreads();
        float a0 = 0.0f, a1 = 0.0f;
        #pragma unroll 1
        for (int c = 0; c < CIN - 1; c += 2) {
            a0 = fmaf(sin[c],     sW[h * CIN + c],     a0);
            a1 = fmaf(sin[c + 1], sW[h * CIN + c + 1], a1);
        }
        a0 = fmaf(sin[CIN - 1], sW[h * CIN + CIN - 1], a0);
        float out = (a0 + a1) * scale + shift;
        __nv_bfloat16 hi = __float2bfloat16(out);
        __nv_bfloat16 lo = __float2bfloat16(out - __bfloat162float(hi));
        __nv_bfloat16* d = dst + row * (long)KS;
        if (isQ) { d[h] = hi; d[HID + h] = lo; d[2 * HID + h] = hi; }
        else     { d[h] = hi; d[HID + h] = hi; d[2 * HID + h] = lo; }
        __syncthreads();
    }
}

// ================= K2: 3-stage pipelined mma.sync bf16 GEMM =================
static constexpr int CH    = 64;
static constexpr int NCH   = KS / CH;             // 6
static constexpr int PITCH = CH * 2 + 16;         // 144 B/row
static constexpr int STG_T = 128 * PITCH;         // 18432
static constexpr int STG   = 2 * STG_T;           // 36864
static constexpr int GEMM_SMEM = 3 * STG;         // 110592

__device__ __forceinline__ void ldsm_x4(uint32_t& r0, uint32_t& r1, uint32_t& r2, uint32_t& r3,
                                        uint32_t addr) {
    asm volatile("ldmatrix.sync.aligned.m8n8.x4.shared.b16 {%0,%1,%2,%3}, [%4];"
                 : "=r"(r0), "=r"(r1), "=r"(r2), "=r"(r3) : "r"(addr));
}
__device__ __forceinline__ void mma_16816(float* c, const uint32_t* a, const uint32_t* b) {
    asm volatile("mma.sync.aligned.m16n8k16.row.col.f32.bf16.bf16.f32 "
                 "{%0,%1,%2,%3}, {%4,%5,%6,%7}, {%8,%9}, {%0,%1,%2,%3};"
                 : "+f"(c[0]), "+f"(c[1]), "+f"(c[2]), "+f"(c[3])
                 : "r"(a[0]), "r"(a[1]), "r"(a[2]), "r"(a[3]), "r"(b[0]), "r"(b[1]));
}
__device__ __forceinline__ void cp16(uint32_t saddr, const void* g) {
    asm volatile("cp.async.cg.shared.global [%0], [%1], 16;" :: "r"(saddr), "l"(g));
}

__device__ __forceinline__ void load_stage(const char* gA, const char* gB,
                                           uint32_t stage_base, int tid)
{
    #pragma unroll
    for (int j = 0; j < 4; j++) {
        int i = tid + j * 256;
        int row = i >> 3, seg = i & 7;
        uint32_t so = (uint32_t)(row * PITCH + seg * 16);
        size_t   go = (size_t)row * (KS * 2) + seg * 16;
        cp16(stage_base + so,         gA + go);
        cp16(stage_base + STG_T + so, gB + go);
    }
    asm volatile("cp.async.commit_group;" ::: "memory");
}

__global__ void __launch_bounds__(256, 2) gemm_kernel(float* __restrict__ out, int b0)
{
    extern __shared__ char smem[];
    uint32_t sbase = smem_to_u32(smem);
    int tid = threadIdx.x, wid = tid >> 5, lane = tid & 31;
    int nb = blockIdx.x, mb = blockIdx.y, b = blockIdx.z + b0;

    const char* gA = reinterpret_cast<const char*>(g_A)  + (size_t)(b * Mm + mb * 128) * KS * 2;
    const char* gB = reinterpret_cast<const char*>(g_Bm) + (size_t)(b * Nn + nb * 128) * KS * 2;

    load_stage(gA,          gB,          sbase,       tid);
    load_stage(gA + CH * 2, gB + CH * 2, sbase + STG, tid);

    int wm = wid >> 2;
    int wn = wid & 3;
    uint32_t aRowOff = (uint32_t)((wm * 64 + (lane & 15)) * PITCH + ((lane >> 4) * 8) * 2);
    uint32_t bRowOff = (uint32_t)(STG_T + (wn * 32 + (lane & 7) + ((lane >> 4) & 1) * 8) * PITCH
                                  + (((lane >> 3) & 1) * 8) * 2);

    float c[4][4][4];
    #pragma unroll
    for (int i = 0; i < 4; i++)
        #pragma unroll
        for (int j = 0; j < 4; j++)
            #pragma unroll
            for (int r = 0; r < 4; r++) c[i][j][r] = 0.0f;

    int st = 0;
    #pragma unroll 1
    for (int ch = 0; ch < NCH; ch++) {
        if (ch < NCH - 2) asm volatile("cp.async.wait_group 1;" ::: "memory");
        else              asm volatile("cp.async.wait_group 0;" ::: "memory");
        __syncthreads();

        if (ch + 2 < NCH) {
            int nst = st + 2; if (nst >= 3) nst -= 3;
            load_stage(gA + (size_t)(ch + 2) * CH * 2, gB + (size_t)(ch + 2) * CH * 2,
                       sbase + nst * STG, tid);
        }

        uint32_t aB = sbase + st * STG + aRowOff;
        uint32_t bB = sbase + st * STG + bRowOff;

        #pragma unroll
        for (int kk = 0; kk < CH / 16; kk++) {
            uint32_t kOff = (uint32_t)(kk * 32);
            uint32_t a[4][4];
            #pragma unroll
            for (int mi = 0; mi < 4; mi++)
                ldsm_x4(a[mi][0], a[mi][1], a[mi][2], a[mi][3],
                        aB + (uint32_t)(mi * 16 * PITCH) + kOff);
            uint32_t bf[4][2];
            #pragma unroll
            for (int p = 0; p < 2; p++) {
                uint32_t r0, r1, r2, r3;
                ldsm_x4(r0, r1, r2, r3, bB + (uint32_t)(p * 16 * PITCH) + kOff);
                bf[2 * p][0] = r0;     bf[2 * p][1] = r1;
                bf[2 * p + 1][0] = r2; bf[2 * p + 1][1] = r3;
            }
            #pragma unroll
            for (int mi = 0; mi < 4; mi++)
                #pragma unroll
                for (int nj = 0; nj < 4; nj++)
                    mma_16816(c[mi][nj], a[mi], bf[nj]);
        }

        if (++st >= 3) st -= 3;
    }

    int g = lane >> 2, tg = lane & 3;
    long rowBase = (long)(b * Mm + mb * 128 + wm * 64);
    int colBase = nb * 128 + wn * 32 + 2 * tg;
    #pragma unroll
    for (int mi = 0; mi < 4; mi++) {
        #pragma unroll
        for (int nj = 0; nj < 4; nj++) {
            float* p0 = out + (rowBase + mi * 16 + g) * Nn + colBase + nj * 8;
            float* p1 = out + (rowBase + mi * 16 + g + 8) * Nn + colBase + nj * 8;
            *reinterpret_cast<float2*>(p0) = make_float2(c[mi][nj][0], c[mi][nj][1]);
            *reinterpret_cast<float2*>(p1) = make_float2(c[mi][nj][2], c[mi][nj][3]);
        }
    }
}

// ================= block reduce helper =================
__device__ __forceinline__ float block_reduce(float v, bool domax, float* red)
{
    int tid = threadIdx.x, lid = tid & 31, wid = tid >> 5;
    #pragma unroll
    for (int o = 16; o; o >>= 1) {
        float t = __shfl_xor_sync(0xffffffffu, v, o);
        v = domax ? fmaxf(v, t) : (v + t);
    }
    if (lid == 0) red[wid] = v;
    __syncthreads();
    if (wid == 0) {
        float w = (lid < 16) ? red[lid] : (domax ? -3.0e38f : 0.0f);
        #pragma unroll
        for (int o = 8; o; o >>= 1) {
            float t = __shfl_xor_sync(0xffffffffu, w, o);
            w = domax ? fmaxf(w, t) : (w + t);
        }
        if (lid == 0) red[0] = w;
    }
    __syncthreads();
    float r = red[0];
    __syncthreads();
    return r;
}

// ================= K3: mask + softmax + sqrt-transform + fused column partials =====
__global__ void __launch_bounds__(512) softmax_kernel(float* __restrict__ buf,
                                                      const float* __restrict__ mask, int b0)
{
    __shared__ float red[16];
    int mblk = blockIdx.x;          // 0..63
    int b = blockIdx.y + b0;
    int tid = threadIdx.x;

    float colacc[8];
    #pragma unroll
    for (int j = 0; j < 8; j++) colacc[j] = 0.0f;

    #pragma unroll 1
    for (int r = 0; r < 16; r++) {
        long row = (long)b * Mm + mblk * 16 + r;
        const float* mrow = mask + row * Nn;
        float* xrow = buf + row * Nn;

        float x[8], mv[8];
        #pragma unroll
        for (int j = 0; j < 8; j++) {
            int n = tid + j * 512;
            x[j] = xrow[n];
            mv[j] = mrow[n];
            if (mv[j] < 1e-9f) x[j] = -1e9f;
        }
        float mx = -3.0e38f;
        #pragma unroll
        for (int j = 0; j < 8; j++) mx = fmaxf(mx, x[j]);
        mx = block_reduce(mx, true, red);

        float e[8], s = 0.0f;
        #pragma unroll
        for (int j = 0; j < 8; j++) { e[j] = __expf(x[j] - mx); s += e[j]; }
        s = block_reduce(s, false, red);
        float inv = 1.0f / s;

        #pragma unroll
        for (int j = 0; j < 8; j++) {
            float p = e[j] * inv;
            float t = sqrtf((mv[j] + 1e-9f) * (p + 1e-9f)) - 1e-9f;
            xrow[tid + j * 512] = t;
            colacc[j] += t;
        }
    }

    float* part = g_partial[mblk] + b * Nn;
    #pragma unroll
    for (int j = 0; j < 8; j++) part[tid + j * 512] = colacc[j];
}

// ================= K3b: finalize column sums (per quarter) =================
__global__ void __launch_bounds__(256) colsum_fin_kernel(int b0)
{
    int i = b0 * Nn + blockIdx.x * 256 + threadIdx.x;
    float s = 0.0f;
    #pragma unroll
    for (int ms = 0; ms < Mm / 16; ms++) s += g_partial[ms][i];
    g_rcolsum[i] = 1.0f / fmaxf(s, 1e-12f);
}

// ================= K4: column norm + row norm (in place, per quarter) =================
__global__ void __launch_bounds__(512) norm_kernel(float* __restrict__ buf, int b0)
{
    __shared__ float red[16];
    long row = (long)b0 * Mm + blockIdx.x;
    int b = (int)(row >> 10);
    float* xrow = buf + row * Nn;
    const float* rc = g_rcolsum + b * Nn;
    int tid = threadIdx.x;

    float u[8], s = 0.0f;
    #pragma unroll
    for (int j = 0; j < 8; j++) {
        int n = tid + j * 512;
        u[j] = xrow[n] * rc[n];
        s += fabsf(u[j]);
    }
    s = block_reduce(s, false, red);
    float inv = 1.0f / fmaxf(s, 1e-12f);
    #pragma unroll
    for (int j = 0; j < 8; j++) xrow[tid + j * 512] = u[j] * inv;
}

// ================= launch (two-stream fork/join overlap) =================
static cudaStream_t g_s2 = nullptr;
static cudaEvent_t g_evG[Bb / QB];
static cudaEvent_t g_evJoin = nullptr;

static void ensure_streams()
{
    if (g_s2 == nullptr) {
        cudaStreamCreateWithFlags(&g_s2, cudaStreamNonBlocking);
        for (int i = 0; i < Bb / QB; i++)
            cudaEventCreateWithFlags(&g_evG[i], cudaEventDisableTiming);
        cudaEventCreateWithFlags(&g_evJoin, cudaEventDisableTiming);
    }
}

extern "C" void kernel_launch(void* const* d_in, const int* in_sizes, int n_in,
                              void* d_out, int out_size)
{
    const float* cent = (const float*)d_in[0];
    const float* feat = (const float*)d_in[1];
    const float* mask = (const float*)d_in[2];
    const float* Wq = (const float*)d_in[3];
    const float* Wk = (const float*)d_in[4];
    const float* gq = (const float*)d_in[5];
    const float* bq = (const float*)d_in[6];
    const float* mq = (const float*)d_in[7];
    const float* vq = (const float*)d_in[8];
    const float* gk = (const float*)d_in[9];
    const float* bk = (const float*)d_in[10];
    const float* mk = (const float*)d_in[11];
    const float* vk = (const float*)d_in[12];
    float* out = (float*)d_out;

    ensure_streams();
    const int NQ = Bb / QB;   // 4 quarters

    // main stream (0): projections, then GEMM quarter by quarter
    qk_kernel<<<(Bb * Mm + Bb * Nn) / 64, 128>>>(cent, feat, Wq, Wk,
                                                 gq, bq, mq, vq, gk, bk, mk, vk);

    cudaFuncSetAttribute(gemm_kernel, cudaFuncAttributeMaxDynamicSharedMemorySize, GEMM_SMEM);
    for (int q = 0; q < NQ; q++) {
        gemm_kernel<<<dim3(Nn / 128, Mm / 128, QB), 256, GEMM_SMEM>>>(out, q * QB);
        cudaEventRecord(g_evG[q], 0);
    }

    // worker stream: softmax -> colsum fin -> norm per quarter, forked on events
    for (int q = 0; q < NQ; q++) {
        cudaStreamWaitEvent(g_s2, g_evG[q], 0);
        softmax_kernel<<<dim3(Mm / 16, QB), 512, 0, g_s2>>>(out, mask, q * QB);
        colsum_fin_kernel<<<(QB * Nn) / 256, 256, 0, g_s2>>>(q * QB);
        norm_kernel<<<QB * Mm, 512, 0, g_s2>>>(out, q * QB);
    }

    // join back to the main stream so the graph's output depends on all work
    cudaEventRecord(g_evJoin, g_s2);
    cudaStreamWaitEvent(0, g_evJoin, 0);
}

// round 11
// speedup vs baseline: 1.1315x; 1.1315x over previous
#include <cuda_runtime.h>
#include <cuda_bf16.h>
#include <cstdint>

// ---------------- problem constants ----------------
static constexpr int Bb  = 16;
static constexpr int Mm  = 1024;
static constexpr int Nn  = 4096;
static constexpr int CIN = 67;
static constexpr int HID = 128;
static constexpr int KS  = 384;          // split-bf16 concat K: [hi|lo|hi] x [hi|hi|lo]

// ---------------- scratch (device globals; no cudaMalloc allowed) ----------------
__device__ __align__(128) __nv_bfloat16 g_A[(size_t)Bb * Mm * KS];   // 12.6 MB
__device__ __align__(128) __nv_bfloat16 g_Bm[(size_t)Bb * Nn * KS]; // 50 MB
__device__ float g_partial[Mm / 16][Bb * Nn];                        // colsum partials (16MB)
__device__ float g_rcolsum[Bb * Nn];                                 // reciprocal col L1 sums
__device__ int   g_rowmaxi[Bb * Mm];                                 // ordered-int row maxes

__device__ __forceinline__ uint32_t smem_to_u32(const void* p) {
    uint32_t a;
    asm("{ .reg .u64 t; cvta.to.shared.u64 t, %1; cvt.u32.u64 %0, t; }" : "=r"(a) : "l"(p));
    return a;
}
// monotone float<->int key (exact, order-invariant max via integer atomicMax)
__device__ __forceinline__ int ordf(float f) {
    int i = __float_as_int(f);
    return i >= 0 ? i : (i ^ 0x7fffffff);
}
__device__ __forceinline__ float ordinv(int i) {
    return __int_as_float(i >= 0 ? i : (i ^ 0x7fffffff));
}

// ================= K0: init row maxes =================
__global__ void __launch_bounds__(256) rowmax_init_kernel()
{
    g_rowmaxi[blockIdx.x * 256 + threadIdx.x] = int(0x80000000);
}

// ================= K1: q/k projection + BN + bf16 split =================
__global__ void __launch_bounds__(128) qk_kernel(
    const float* __restrict__ cent, const float* __restrict__ feat,
    const float* __restrict__ Wq, const float* __restrict__ Wk,
    const float* __restrict__ gq, const float* __restrict__ bq,
    const float* __restrict__ mq, const float* __restrict__ vq,
    const float* __restrict__ gk, const float* __restrict__ bk,
    const float* __restrict__ mk, const float* __restrict__ vk)
{
    __shared__ float sW[HID * CIN];
    __shared__ float sin[CIN];
    const int ROWS = 64;
    long row0 = (long)blockIdx.x * ROWS;
    bool isQ = row0 < (long)Bb * Mm;
    const float* W = isQ ? Wq : Wk;
    for (int i = threadIdx.x; i < HID * CIN; i += blockDim.x) sW[i] = W[i];

    int h = threadIdx.x;
    float g_ = isQ ? gq[h] : gk[h];
    float b_ = isQ ? bq[h] : bk[h];
    float m_ = isQ ? mq[h] : mk[h];
    float v_ = isQ ? vq[h] : vk[h];
    float scale = g_ / sqrtf(v_ + 1e-5f);
    float shift = b_ - m_ * scale;

    const float* X = isQ ? cent : feat;
    long rbase = isQ ? row0 : row0 - (long)Bb * Mm;
    __nv_bfloat16* dst = isQ ? g_A : g_Bm;
    __syncthreads();

    for (int r = 0; r < ROWS; r++) {
        long row = rbase + r;
        if (threadIdx.x < CIN) sin[threadIdx.x] = X[row * CIN + threadIdx.x];
        __syncthreads();
        float a0 = 0.0f, a1 = 0.0f;
        #pragma unroll 1
        for (int c = 0; c < CIN - 1; c += 2) {
            a0 = fmaf(sin[c],     sW[h * CIN + c],     a0);
            a1 = fmaf(sin[c + 1], sW[h * CIN + c + 1], a1);
        }
        a0 = fmaf(sin[CIN - 1], sW[h * CIN + CIN - 1], a0);
        float out = (a0 + a1) * scale + shift;
        __nv_bfloat16 hi = __float2bfloat16(out);
        __nv_bfloat16 lo = __float2bfloat16(out - __bfloat162float(hi));
        __nv_bfloat16* d = dst + row * (long)KS;
        if (isQ) { d[h] = hi; d[HID + h] = lo; d[2 * HID + h] = hi; }
        else     { d[h] = hi; d[HID + h] = hi; d[2 * HID + h] = lo; }
        __syncthreads();
    }
}

// ================= K2: 3-stage pipelined mma.sync bf16 GEMM + rowmax =================
static constexpr int CH    = 64;
static constexpr int NCH   = KS / CH;             // 6
static constexpr int PITCH = CH * 2 + 16;         // 144 B/row
static constexpr int STG_T = 128 * PITCH;         // 18432
static constexpr int STG   = 2 * STG_T;           // 36864
static constexpr int GEMM_SMEM = 3 * STG;         // 110592

__device__ __forceinline__ void ldsm_x4(uint32_t& r0, uint32_t& r1, uint32_t& r2, uint32_t& r3,
                                        uint32_t addr) {
    asm volatile("ldmatrix.sync.aligned.m8n8.x4.shared.b16 {%0,%1,%2,%3}, [%4];"
                 : "=r"(r0), "=r"(r1), "=r"(r2), "=r"(r3) : "r"(addr));
}
__device__ __forceinline__ void mma_16816(float* c, const uint32_t* a, const uint32_t* b) {
    asm volatile("mma.sync.aligned.m16n8k16.row.col.f32.bf16.bf16.f32 "
                 "{%0,%1,%2,%3}, {%4,%5,%6,%7}, {%8,%9}, {%0,%1,%2,%3};"
                 : "+f"(c[0]), "+f"(c[1]), "+f"(c[2]), "+f"(c[3])
                 : "r"(a[0]), "r"(a[1]), "r"(a[2]), "r"(a[3]), "r"(b[0]), "r"(b[1]));
}
__device__ __forceinline__ void cp16(uint32_t saddr, const void* g) {
    asm volatile("cp.async.cg.shared.global [%0], [%1], 16;" :: "r"(saddr), "l"(g));
}

__device__ __forceinline__ void load_stage(const char* gA, const char* gB,
                                           uint32_t stage_base, int tid)
{
    #pragma unroll
    for (int j = 0; j < 4; j++) {
        int i = tid + j * 256;
        int row = i >> 3, seg = i & 7;
        uint32_t so = (uint32_t)(row * PITCH + seg * 16);
        size_t   go = (size_t)row * (KS * 2) + seg * 16;
        cp16(stage_base + so,         gA + go);
        cp16(stage_base + STG_T + so, gB + go);
    }
    asm volatile("cp.async.commit_group;" ::: "memory");
}

__global__ void __launch_bounds__(256, 2) gemm_kernel(float* __restrict__ out)
{
    extern __shared__ char smem[];
    uint32_t sbase = smem_to_u32(smem);
    int tid = threadIdx.x, wid = tid >> 5, lane = tid & 31;
    int nb = blockIdx.x, mb = blockIdx.y, b = blockIdx.z;

    const char* gA = reinterpret_cast<const char*>(g_A)  + (size_t)(b * Mm + mb * 128) * KS * 2;
    const char* gB = reinterpret_cast<const char*>(g_Bm) + (size_t)(b * Nn + nb * 128) * KS * 2;

    load_stage(gA,          gB,          sbase,       tid);
    load_stage(gA + CH * 2, gB + CH * 2, sbase + STG, tid);

    int wm = wid >> 2;
    int wn = wid & 3;
    uint32_t aRowOff = (uint32_t)((wm * 64 + (lane & 15)) * PITCH + ((lane >> 4) * 8) * 2);
    uint32_t bRowOff = (uint32_t)(STG_T + (wn * 32 + (lane & 7) + ((lane >> 4) & 1) * 8) * PITCH
                                  + (((lane >> 3) & 1) * 8) * 2);

    float c[4][4][4];
    #pragma unroll
    for (int i = 0; i < 4; i++)
        #pragma unroll
        for (int j = 0; j < 4; j++)
            #pragma unroll
            for (int r = 0; r < 4; r++) c[i][j][r] = 0.0f;

    int st = 0;
    #pragma unroll 1
    for (int ch = 0; ch < NCH; ch++) {
        if (ch < NCH - 2) asm volatile("cp.async.wait_group 1;" ::: "memory");
        else              asm volatile("cp.async.wait_group 0;" ::: "memory");
        __syncthreads();

        if (ch + 2 < NCH) {
            int nst = st + 2; if (nst >= 3) nst -= 3;
            load_stage(gA + (size_t)(ch + 2) * CH * 2, gB + (size_t)(ch + 2) * CH * 2,
                       sbase + nst * STG, tid);
        }

        uint32_t aB = sbase + st * STG + aRowOff;
        uint32_t bB = sbase + st * STG + bRowOff;

        #pragma unroll
        for (int kk = 0; kk < CH / 16; kk++) {
            uint32_t kOff = (uint32_t)(kk * 32);
            uint32_t a[4][4];
            #pragma unroll
            for (int mi = 0; mi < 4; mi++)
                ldsm_x4(a[mi][0], a[mi][1], a[mi][2], a[mi][3],
                        aB + (uint32_t)(mi * 16 * PITCH) + kOff);
            uint32_t bf[4][2];
            #pragma unroll
            for (int p = 0; p < 2; p++) {
                uint32_t r0, r1, r2, r3;
                ldsm_x4(r0, r1, r2, r3, bB + (uint32_t)(p * 16 * PITCH) + kOff);
                bf[2 * p][0] = r0;     bf[2 * p][1] = r1;
                bf[2 * p + 1][0] = r2; bf[2 * p + 1][1] = r3;
            }
            #pragma unroll
            for (int mi = 0; mi < 4; mi++)
                #pragma unroll
                for (int nj = 0; nj < 4; nj++)
                    mma_16816(c[mi][nj], a[mi], bf[nj]);
        }

        if (++st >= 3) st -= 3;
    }

    // ---- epilogue: write logits + CTA row-max -> global ordered-int atomicMax ----
    int* srm = reinterpret_cast<int*>(smem);       // reuse pipeline smem
    __syncthreads();
    if (tid < 128) srm[tid] = int(0x80000000);
    __syncthreads();

    int g = lane >> 2, tg = lane & 3;
    long rowBase = (long)(b * Mm + mb * 128 + wm * 64);
    int colBase = nb * 128 + wn * 32 + 2 * tg;
    #pragma unroll
    for (int mi = 0; mi < 4; mi++) {
        float v0 = -3.0e38f, v1 = -3.0e38f;
        #pragma unroll
        for (int nj = 0; nj < 4; nj++) {
            float* p0 = out + (rowBase + mi * 16 + g) * Nn + colBase + nj * 8;
            float* p1 = out + (rowBase + mi * 16 + g + 8) * Nn + colBase + nj * 8;
            *reinterpret_cast<float2*>(p0) = make_float2(c[mi][nj][0], c[mi][nj][1]);
            *reinterpret_cast<float2*>(p1) = make_float2(c[mi][nj][2], c[mi][nj][3]);
            v0 = fmaxf(v0, fmaxf(c[mi][nj][0], c[mi][nj][1]));
            v1 = fmaxf(v1, fmaxf(c[mi][nj][2], c[mi][nj][3]));
        }
        atomicMax(&srm[wm * 64 + mi * 16 + g],     ordf(v0));
        atomicMax(&srm[wm * 64 + mi * 16 + g + 8], ordf(v1));
    }
    __syncthreads();
    if (tid < 128)
        atomicMax(&g_rowmaxi[b * Mm + mb * 128 + tid], srm[tid]);
}

// ================= block sum reduce (512 threads = 16 warps) =================
__device__ __forceinline__ float block_sum(float v, float* red)
{
    int tid = threadIdx.x, lid = tid & 31, wid = tid >> 5;
    #pragma unroll
    for (int o = 16; o; o >>= 1) v += __shfl_xor_sync(0xffffffffu, v, o);
    if (lid == 0) red[wid] = v;
    __syncthreads();
    if (wid == 0) {
        float w = (lid < 16) ? red[lid] : 0.0f;
        #pragma unroll
        for (int o = 8; o; o >>= 1) w += __shfl_xor_sync(0xffffffffu, w, o);
        if (lid == 0) red[0] = w;
    }
    __syncthreads();
    float r = red[0];
    __syncthreads();
    return r;
}

// ================= K3: softmax (precomputed rowmax) + sqrt-transform + col partials =====
// 16 rows per CTA, float4, next-row loads pipelined past the sum reduce.
__global__ void __launch_bounds__(512) softmax_kernel(float* __restrict__ buf,
                                                      const float* __restrict__ mask)
{
    __shared__ float red[16];
    int mblk = blockIdx.x;          // 0..63
    int b = blockIdx.y;             // 0..15
    int tid = threadIdx.x;
    long row0 = (long)b * Mm + mblk * 16;

    float ca[8];
    #pragma unroll
    for (int j = 0; j < 8; j++) ca[j] = 0.0f;

    float4 x[2], mv[2];
    {
        const float4* xr = reinterpret_cast<const float4*>(buf + row0 * Nn);
        const float4* mr = reinterpret_cast<const float4*>(mask + row0 * Nn);
        x[0] = xr[tid]; x[1] = xr[tid + 512];
        mv[0] = mr[tid]; mv[1] = mr[tid + 512];
    }

    #pragma unroll 1
    for (int r = 0; r < 16; r++) {
        long row = row0 + r;
        float rm = ordinv(g_rowmaxi[row]);

        // consume current row: e, mq, partial sum
        float e[8], mq[8], s = 0.0f;
        #pragma unroll
        for (int j = 0; j < 2; j++) {
            const float* xp = reinterpret_cast<const float*>(&x[j]);
            const float* mp = reinterpret_cast<const float*>(&mv[j]);
            #pragma unroll
            for (int k = 0; k < 4; k++) {
                float m = mp[k];
                float xi = (m < 1e-9f) ? -1e9f : xp[k];
                float ev = __expf(xi - rm);
                e[j * 4 + k] = ev;
                mq[j * 4 + k] = m + 1e-9f;
                s += ev;
            }
        }

        // prefetch next row while the reduce runs
        if (r < 15) {
            const float4* xr = reinterpret_cast<const float4*>(buf + (row + 1) * Nn);
            const float4* mr = reinterpret_cast<const float4*>(mask + (row + 1) * Nn);
            x[0] = xr[tid]; x[1] = xr[tid + 512];
            mv[0] = mr[tid]; mv[1] = mr[tid + 512];
        }

        s = block_sum(s, red);
        float inv = 1.0f / s;

        float4* xw = reinterpret_cast<float4*>(buf + row * Nn);
        #pragma unroll
        for (int j = 0; j < 2; j++) {
            float4 o;
            float* op = reinterpret_cast<float*>(&o);
            #pragma unroll
            for (int k = 0; k < 4; k++) {
                float p = e[j * 4 + k] * inv;
                float t = sqrtf(mq[j * 4 + k] * (p + 1e-9f)) - 1e-9f;
                op[k] = t;
                ca[j * 4 + k] += t;
            }
            xw[tid + j * 512] = o;
        }
    }

    float4* part = reinterpret_cast<float4*>(g_partial[mblk] + b * Nn);
    #pragma unroll
    for (int j = 0; j < 2; j++) {
        float4 o;
        o.x = ca[j * 4 + 0]; o.y = ca[j * 4 + 1];
        o.z = ca[j * 4 + 2]; o.w = ca[j * 4 + 3];
        part[tid + j * 512] = o;
    }
}

// ================= K3b: finalize column sums =================
__global__ void __launch_bounds__(256) colsum_fin_kernel()
{
    int i = blockIdx.x * 256 + threadIdx.x;
    float s = 0.0f;
    #pragma unroll
    for (int ms = 0; ms < Mm / 16; ms++) s += g_partial[ms][i];
    g_rcolsum[i] = 1.0f / fmaxf(s, 1e-12f);
}

// ================= K4: column norm + row norm (in place, float4) =================
__global__ void __launch_bounds__(512) norm_kernel(float* __restrict__ buf)
{
    __shared__ float red[16];
    long row = blockIdx.x;
    int b = (int)(row >> 10);
    float4* xrow = reinterpret_cast<float4*>(buf + row * Nn);
    const float4* rc = reinterpret_cast<const float4*>(g_rcolsum + b * Nn);
    int tid = threadIdx.x;

    float4 u[2];
    float s = 0.0f;
    #pragma unroll
    for (int j = 0; j < 2; j++) {
        float4 t = xrow[tid + j * 512];
        float4 r = rc[tid + j * 512];
        u[j].x = t.x * r.x; u[j].y = t.y * r.y;
        u[j].z = t.z * r.z; u[j].w = t.w * r.w;
        s += u[j].x + u[j].y + u[j].z + u[j].w;   // u >= 0
    }
    s = block_sum(s, red);
    float inv = 1.0f / fmaxf(s, 1e-12f);
    #pragma unroll
    for (int j = 0; j < 2; j++) {
        float4 o;
        o.x = u[j].x * inv; o.y = u[j].y * inv;
        o.z = u[j].z * inv; o.w = u[j].w * inv;
        xrow[tid + j * 512] = o;
    }
}

// ================= launch =================
extern "C" void kernel_launch(void* const* d_in, const int* in_sizes, int n_in,
                              void* d_out, int out_size)
{
    const float* cent = (const float*)d_in[0];
    const float* feat = (const float*)d_in[1];
    const float* mask = (const float*)d_in[2];
    const float* Wq = (const float*)d_in[3];
    const float* Wk = (const float*)d_in[4];
    const float* gq = (const float*)d_in[5];
    const float* bq = (const float*)d_in[6];
    const float* mq = (const float*)d_in[7];
    const float* vq = (const float*)d_in[8];
    const float* gk = (const float*)d_in[9];
    const float* bk = (const float*)d_in[10];
    const float* mk = (const float*)d_in[11];
    const float* vk = (const float*)d_in[12];
    float* out = (float*)d_out;

    rowmax_init_kernel<<<(Bb * Mm) / 256, 256>>>();

    qk_kernel<<<(Bb * Mm + Bb * Nn) / 64, 128>>>(cent, feat, Wq, Wk,
                                                 gq, bq, mq, vq, gk, bk, mk, vk);

    cudaFuncSetAttribute(gemm_kernel, cudaFuncAttributeMaxDynamicSharedMemorySize, GEMM_SMEM);
    gemm_kernel<<<dim3(Nn / 128, Mm / 128, Bb), 256, GEMM_SMEM>>>(out);

    softmax_kernel<<<dim3(Mm / 16, Bb), 512>>>(out, mask);

    colsum_fin_kernel<<<(Bb * Nn) / 256, 256>>>();

    norm_kernel<<<Bb * Mm, 512>>>(out);
}

// round 12
// speedup vs baseline: 1.1446x; 1.0116x over previous
#include <cuda_runtime.h>
#include <cuda_bf16.h>
#include <cstdint>

// ---------------- problem constants ----------------
static constexpr int Bb  = 16;
static constexpr int Mm  = 1024;
static constexpr int Nn  = 4096;
static constexpr int CIN = 67;
static constexpr int HID = 128;
static constexpr int KS  = 384;          // split-bf16 concat K: [hi|lo|hi] x [hi|hi|lo]

// ---------------- scratch (device globals; no cudaMalloc allowed) ----------------
__device__ __align__(128) __nv_bfloat16 g_A[(size_t)Bb * Mm * KS];   // 12.6 MB
__device__ __align__(128) __nv_bfloat16 g_Bm[(size_t)Bb * Nn * KS]; // 50 MB
__device__ float g_partial[Mm / 16][Bb * Nn];                        // colsum partials (16MB)
__device__ float g_rcolsum[Bb * Nn];                                 // reciprocal col L1 sums

__device__ __forceinline__ uint32_t smem_to_u32(const void* p) {
    uint32_t a;
    asm("{ .reg .u64 t; cvta.to.shared.u64 t, %1; cvt.u32.u64 %0, t; }" : "=r"(a) : "l"(p));
    return a;
}

// ================= K1: q/k projection + BN + bf16 split =================
__global__ void __launch_bounds__(128) qk_kernel(
    const float* __restrict__ cent, const float* __restrict__ feat,
    const float* __restrict__ Wq, const float* __restrict__ Wk,
    const float* __restrict__ gq, const float* __restrict__ bq,
    const float* __restrict__ mq, const float* __restrict__ vq,
    const float* __restrict__ gk, const float* __restrict__ bk,
    const float* __restrict__ mk, const float* __restrict__ vk)
{
    __shared__ float sW[HID * CIN];
    __shared__ float sin[CIN];
    const int ROWS = 64;
    long row0 = (long)blockIdx.x * ROWS;
    bool isQ = row0 < (long)Bb * Mm;
    const float* W = isQ ? Wq : Wk;
    for (int i = threadIdx.x; i < HID * CIN; i += blockDim.x) sW[i] = W[i];

    int h = threadIdx.x;
    float g_ = isQ ? gq[h] : gk[h];
    float b_ = isQ ? bq[h] : bk[h];
    float m_ = isQ ? mq[h] : mk[h];
    float v_ = isQ ? vq[h] : vk[h];
    float scale = g_ / sqrtf(v_ + 1e-5f);
    float shift = b_ - m_ * scale;

    const float* X = isQ ? cent : feat;
    long rbase = isQ ? row0 : row0 - (long)Bb * Mm;
    __nv_bfloat16* dst = isQ ? g_A : g_Bm;
    __syncthreads();

    for (int r = 0; r < ROWS; r++) {
        long row = rbase + r;
        if (threadIdx.x < CIN) sin[threadIdx.x] = X[row * CIN + threadIdx.x];
        __syncthreads();
        float a0 = 0.0f, a1 = 0.0f;
        #pragma unroll 1
        for (int c = 0; c < CIN - 1; c += 2) {
            a0 = fmaf(sin[c],     sW[h * CIN + c],     a0);
            a1 = fmaf(sin[c + 1], sW[h * CIN + c + 1], a1);
        }
        a0 = fmaf(sin[CIN - 1], sW[h * CIN + CIN - 1], a0);
        float out = (a0 + a1) * scale + shift;
        __nv_bfloat16 hi = __float2bfloat16(out);
        __nv_bfloat16 lo = __float2bfloat16(out - __bfloat162float(hi));
        __nv_bfloat16* d = dst + row * (long)KS;
        if (isQ) { d[h] = hi; d[HID + h] = lo; d[2 * HID + h] = hi; }
        else     { d[h] = hi; d[HID + h] = hi; d[2 * HID + h] = lo; }
        __syncthreads();
    }
}

// ================= K2: 3-stage pipelined mma.sync bf16 GEMM (R10 epilogue) =============
static constexpr int CH    = 64;
static constexpr int NCH   = KS / CH;             // 6
static constexpr int PITCH = CH * 2 + 16;         // 144 B/row
static constexpr int STG_T = 128 * PITCH;         // 18432
static constexpr int STG   = 2 * STG_T;           // 36864
static constexpr int GEMM_SMEM = 3 * STG;         // 110592

__device__ __forceinline__ void ldsm_x4(uint32_t& r0, uint32_t& r1, uint32_t& r2, uint32_t& r3,
                                        uint32_t addr) {
    asm volatile("ldmatrix.sync.aligned.m8n8.x4.shared.b16 {%0,%1,%2,%3}, [%4];"
                 : "=r"(r0), "=r"(r1), "=r"(r2), "=r"(r3) : "r"(addr));
}
__device__ __forceinline__ void mma_16816(float* c, const uint32_t* a, const uint32_t* b) {
    asm volatile("mma.sync.aligned.m16n8k16.row.col.f32.bf16.bf16.f32 "
                 "{%0,%1,%2,%3}, {%4,%5,%6,%7}, {%8,%9}, {%0,%1,%2,%3};"
                 : "+f"(c[0]), "+f"(c[1]), "+f"(c[2]), "+f"(c[3])
                 : "r"(a[0]), "r"(a[1]), "r"(a[2]), "r"(a[3]), "r"(b[0]), "r"(b[1]));
}
__device__ __forceinline__ void cp16(uint32_t saddr, const void* g) {
    asm volatile("cp.async.cg.shared.global [%0], [%1], 16;" :: "r"(saddr), "l"(g));
}

__device__ __forceinline__ void load_stage(const char* gA, const char* gB,
                                           uint32_t stage_base, int tid)
{
    #pragma unroll
    for (int j = 0; j < 4; j++) {
        int i = tid + j * 256;
        int row = i >> 3, seg = i & 7;
        uint32_t so = (uint32_t)(row * PITCH + seg * 16);
        size_t   go = (size_t)row * (KS * 2) + seg * 16;
        cp16(stage_base + so,         gA + go);
        cp16(stage_base + STG_T + so, gB + go);
    }
    asm volatile("cp.async.commit_group;" ::: "memory");
}

__global__ void __launch_bounds__(256, 2) gemm_kernel(float* __restrict__ out)
{
    extern __shared__ char smem[];
    uint32_t sbase = smem_to_u32(smem);
    int tid = threadIdx.x, wid = tid >> 5, lane = tid & 31;
    int nb = blockIdx.x, mb = blockIdx.y, b = blockIdx.z;

    const char* gA = reinterpret_cast<const char*>(g_A)  + (size_t)(b * Mm + mb * 128) * KS * 2;
    const char* gB = reinterpret_cast<const char*>(g_Bm) + (size_t)(b * Nn + nb * 128) * KS * 2;

    load_stage(gA,          gB,          sbase,       tid);
    load_stage(gA + CH * 2, gB + CH * 2, sbase + STG, tid);

    int wm = wid >> 2;
    int wn = wid & 3;
    uint32_t aRowOff = (uint32_t)((wm * 64 + (lane & 15)) * PITCH + ((lane >> 4) * 8) * 2);
    uint32_t bRowOff = (uint32_t)(STG_T + (wn * 32 + (lane & 7) + ((lane >> 4) & 1) * 8) * PITCH
                                  + (((lane >> 3) & 1) * 8) * 2);

    float c[4][4][4];
    #pragma unroll
    for (int i = 0; i < 4; i++)
        #pragma unroll
        for (int j = 0; j < 4; j++)
            #pragma unroll
            for (int r = 0; r < 4; r++) c[i][j][r] = 0.0f;

    int st = 0;
    #pragma unroll 1
    for (int ch = 0; ch < NCH; ch++) {
        if (ch < NCH - 2) asm volatile("cp.async.wait_group 1;" ::: "memory");
        else              asm volatile("cp.async.wait_group 0;" ::: "memory");
        __syncthreads();

        if (ch + 2 < NCH) {
            int nst = st + 2; if (nst >= 3) nst -= 3;
            load_stage(gA + (size_t)(ch + 2) * CH * 2, gB + (size_t)(ch + 2) * CH * 2,
                       sbase + nst * STG, tid);
        }

        uint32_t aB = sbase + st * STG + aRowOff;
        uint32_t bB = sbase + st * STG + bRowOff;

        #pragma unroll
        for (int kk = 0; kk < CH / 16; kk++) {
            uint32_t kOff = (uint32_t)(kk * 32);
            uint32_t a[4][4];
            #pragma unroll
            for (int mi = 0; mi < 4; mi++)
                ldsm_x4(a[mi][0], a[mi][1], a[mi][2], a[mi][3],
                        aB + (uint32_t)(mi * 16 * PITCH) + kOff);
            uint32_t bf[4][2];
            #pragma unroll
            for (int p = 0; p < 2; p++) {
                uint32_t r0, r1, r2, r3;
                ldsm_x4(r0, r1, r2, r3, bB + (uint32_t)(p * 16 * PITCH) + kOff);
                bf[2 * p][0] = r0;     bf[2 * p][1] = r1;
                bf[2 * p + 1][0] = r2; bf[2 * p + 1][1] = r3;
            }
            #pragma unroll
            for (int mi = 0; mi < 4; mi++)
                #pragma unroll
                for (int nj = 0; nj < 4; nj++)
                    mma_16816(c[mi][nj], a[mi], bf[nj]);
        }

        if (++st >= 3) st -= 3;
    }

    int g = lane >> 2, tg = lane & 3;
    long rowBase = (long)(b * Mm + mb * 128 + wm * 64);
    int colBase = nb * 128 + wn * 32 + 2 * tg;
    #pragma unroll
    for (int mi = 0; mi < 4; mi++) {
        #pragma unroll
        for (int nj = 0; nj < 4; nj++) {
            float* p0 = out + (rowBase + mi * 16 + g) * Nn + colBase + nj * 8;
            float* p1 = out + (rowBase + mi * 16 + g + 8) * Nn + colBase + nj * 8;
            *reinterpret_cast<float2*>(p0) = make_float2(c[mi][nj][0], c[mi][nj][1]);
            *reinterpret_cast<float2*>(p1) = make_float2(c[mi][nj][2], c[mi][nj][3]);
        }
    }
}

// ================= block reduce helpers (512 threads = 16 warps) =================
__device__ __forceinline__ float block_sum(float v, float* red)
{
    int tid = threadIdx.x, lid = tid & 31, wid = tid >> 5;
    #pragma unroll
    for (int o = 16; o; o >>= 1) v += __shfl_xor_sync(0xffffffffu, v, o);
    if (lid == 0) red[wid] = v;
    __syncthreads();
    if (wid == 0) {
        float w = (lid < 16) ? red[lid] : 0.0f;
        #pragma unroll
        for (int o = 8; o; o >>= 1) w += __shfl_xor_sync(0xffffffffu, w, o);
        if (lid == 0) red[0] = w;
    }
    __syncthreads();
    float r = red[0];
    __syncthreads();
    return r;
}
__device__ __forceinline__ float block_max(float v, float* red)
{
    int tid = threadIdx.x, lid = tid & 31, wid = tid >> 5;
    #pragma unroll
    for (int o = 16; o; o >>= 1) v = fmaxf(v, __shfl_xor_sync(0xffffffffu, v, o));
    if (lid == 0) red[wid] = v;
    __syncthreads();
    if (wid == 0) {
        float w = (lid < 16) ? red[lid] : -3.0e38f;
        #pragma unroll
        for (int o = 8; o; o >>= 1) w = fmaxf(w, __shfl_xor_sync(0xffffffffu, w, o));
        if (lid == 0) red[0] = w;
    }
    __syncthreads();
    float r = red[0];
    __syncthreads();
    return r;
}

// ================= K3: softmax (in-kernel max) + sqrt-transform + col partials =====
// 16 rows per CTA, float4, next-row prefetch issued before BOTH reduces.
__global__ void __launch_bounds__(512) softmax_kernel(float* __restrict__ buf,
                                                      const float* __restrict__ mask)
{
    __shared__ float red[16];
    int mblk = blockIdx.x;          // 0..63
    int b = blockIdx.y;             // 0..15
    int tid = threadIdx.x;
    long row0 = (long)b * Mm + mblk * 16;

    float ca[8];
    #pragma unroll
    for (int j = 0; j < 8; j++) ca[j] = 0.0f;

    float4 x[2], mv[2];
    {
        const float4* xr = reinterpret_cast<const float4*>(buf + row0 * Nn);
        const float4* mr = reinterpret_cast<const float4*>(mask + row0 * Nn);
        x[0] = xr[tid]; x[1] = xr[tid + 512];
        mv[0] = mr[tid]; mv[1] = mr[tid + 512];
    }

    #pragma unroll 1
    for (int r = 0; r < 16; r++) {
        long row = row0 + r;

        // consume current row into xi/mq registers, freeing x/mv for prefetch
        float xi[8], mq[8];
        float lmx = -3.0e38f;
        #pragma unroll
        for (int j = 0; j < 2; j++) {
            const float* xp = reinterpret_cast<const float*>(&x[j]);
            const float* mp = reinterpret_cast<const float*>(&mv[j]);
            #pragma unroll
            for (int k = 0; k < 4; k++) {
                float m = mp[k];
                float v = (m < 1e-9f) ? -1e9f : xp[k];
                xi[j * 4 + k] = v;
                mq[j * 4 + k] = m + 1e-9f;
                lmx = fmaxf(lmx, v);
            }
        }

        // prefetch next row while both reduces run
        if (r < 15) {
            const float4* xr = reinterpret_cast<const float4*>(buf + (row + 1) * Nn);
            const float4* mr = reinterpret_cast<const float4*>(mask + (row + 1) * Nn);
            x[0] = xr[tid]; x[1] = xr[tid + 512];
            mv[0] = mr[tid]; mv[1] = mr[tid + 512];
        }

        float rm = block_max(lmx, red);

        float s = 0.0f;
        #pragma unroll
        for (int j = 0; j < 8; j++) { xi[j] = __expf(xi[j] - rm); s += xi[j]; }
        s = block_sum(s, red);
        float inv = 1.0f / s;

        float4* xw = reinterpret_cast<float4*>(buf + row * Nn);
        #pragma unroll
        for (int j = 0; j < 2; j++) {
            float4 o;
            float* op = reinterpret_cast<float*>(&o);
            #pragma unroll
            for (int k = 0; k < 4; k++) {
                float p = xi[j * 4 + k] * inv;
                float t = sqrtf(mq[j * 4 + k] * (p + 1e-9f)) - 1e-9f;
                op[k] = t;
                ca[j * 4 + k] += t;
            }
            xw[tid + j * 512] = o;
        }
    }

    float4* part = reinterpret_cast<float4*>(g_partial[mblk] + b * Nn);
    #pragma unroll
    for (int j = 0; j < 2; j++) {
        float4 o;
        o.x = ca[j * 4 + 0]; o.y = ca[j * 4 + 1];
        o.z = ca[j * 4 + 2]; o.w = ca[j * 4 + 3];
        part[tid + j * 512] = o;
    }
}

// ================= K3b: finalize column sums =================
__global__ void __launch_bounds__(256) colsum_fin_kernel()
{
    int i = blockIdx.x * 256 + threadIdx.x;
    float s = 0.0f;
    #pragma unroll
    for (int ms = 0; ms < Mm / 16; ms++) s += g_partial[ms][i];
    g_rcolsum[i] = 1.0f / fmaxf(s, 1e-12f);
}

// ================= K4: column norm + row norm (in place, float4) =================
__global__ void __launch_bounds__(512) norm_kernel(float* __restrict__ buf)
{
    __shared__ float red[16];
    long row = blockIdx.x;
    int b = (int)(row >> 10);
    float4* xrow = reinterpret_cast<float4*>(buf + row * Nn);
    const float4* rc = reinterpret_cast<const float4*>(g_rcolsum + b * Nn);
    int tid = threadIdx.x;

    float4 u[2];
    float s = 0.0f;
    #pragma unroll
    for (int j = 0; j < 2; j++) {
        float4 t = xrow[tid + j * 512];
        float4 r = rc[tid + j * 512];
        u[j].x = t.x * r.x; u[j].y = t.y * r.y;
        u[j].z = t.z * r.z; u[j].w = t.w * r.w;
        s += u[j].x + u[j].y + u[j].z + u[j].w;
    }
    s = block_sum(s, red);
    float inv = 1.0f / fmaxf(s, 1e-12f);
    #pragma unroll
    for (int j = 0; j < 2; j++) {
        float4 o;
        o.x = u[j].x * inv; o.y = u[j].y * inv;
        o.z = u[j].z * inv; o.w = u[j].w * inv;
        xrow[tid + j * 512] = o;
    }
}

// ================= launch =================
extern "C" void kernel_launch(void* const* d_in, const int* in_sizes, int n_in,
                              void* d_out, int out_size)
{
    const float* cent = (const float*)d_in[0];
    const float* feat = (const float*)d_in[1];
    const float* mask = (const float*)d_in[2];
    const float* Wq = (const float*)d_in[3];
    const float* Wk = (const float*)d_in[4];
    const float* gq = (const float*)d_in[5];
    const float* bq = (const float*)d_in[6];
    const float* mq = (const float*)d_in[7];
    const float* vq = (const float*)d_in[8];
    const float* gk = (const float*)d_in[9];
    const float* bk = (const float*)d_in[10];
    const float* mk = (const float*)d_in[11];
    const float* vk = (const float*)d_in[12];
    float* out = (float*)d_out;

    qk_kernel<<<(Bb * Mm + Bb * Nn) / 64, 128>>>(cent, feat, Wq, Wk,
                                                 gq, bq, mq, vq, gk, bk, mk, vk);

    cudaFuncSetAttribute(gemm_kernel, cudaFuncAttributeMaxDynamicSharedMemorySize, GEMM_SMEM);
    gemm_kernel<<<dim3(Nn / 128, Mm / 128, Bb), 256, GEMM_SMEM>>>(out);

    softmax_kernel<<<dim3(Mm / 16, Bb), 512>>>(out, mask);

    colsum_fin_kernel<<<(Bb * Nn) / 256, 256>>>();

    norm_kernel<<<Bb * Mm, 512>>>(out);
}

// round 13
// speedup vs baseline: 1.2123x; 1.0591x over previous
#include <cuda_runtime.h>
#include <cuda_bf16.h>
#include <cuda_fp16.h>
#include <cstdint>

// ---------------- problem constants ----------------
static constexpr int Bb  = 16;
static constexpr int Mm  = 1024;
static constexpr int Nn  = 4096;
static constexpr int CIN = 67;
static constexpr int HID = 128;
static constexpr int KS  = 384;          // split-bf16 concat K: [hi|lo|hi] x [hi|hi|lo]

// ---------------- scratch (device globals; no cudaMalloc allowed) ----------------
__device__ __align__(128) __nv_bfloat16 g_A[(size_t)Bb * Mm * KS];   // 12.6 MB
__device__ __align__(128) __nv_bfloat16 g_Bm[(size_t)Bb * Nn * KS]; // 50 MB
__device__ __align__(128) __half g_T[(size_t)Bb * Mm * Nn];          // 134 MB (t, fp16)
__device__ float g_partial[Mm / 16][Bb * Nn];                        // colsum partials (16MB)
__device__ float g_rcolsum[Bb * Nn];                                 // reciprocal col L1 sums

__device__ __forceinline__ uint32_t smem_to_u32(const void* p) {
    uint32_t a;
    asm("{ .reg .u64 t; cvta.to.shared.u64 t, %1; cvt.u32.u64 %0, t; }" : "=r"(a) : "l"(p));
    return a;
}

// ================= K1: q/k projection + BN + bf16 split =================
__global__ void __launch_bounds__(128) qk_kernel(
    const float* __restrict__ cent, const float* __restrict__ feat,
    const float* __restrict__ Wq, const float* __restrict__ Wk,
    const float* __restrict__ gq, const float* __restrict__ bq,
    const float* __restrict__ mq, const float* __restrict__ vq,
    const float* __restrict__ gk, const float* __restrict__ bk,
    const float* __restrict__ mk, const float* __restrict__ vk)
{
    __shared__ float sW[HID * CIN];
    __shared__ float sin[CIN];
    const int ROWS = 64;
    long row0 = (long)blockIdx.x * ROWS;
    bool isQ = row0 < (long)Bb * Mm;
    const float* W = isQ ? Wq : Wk;
    for (int i = threadIdx.x; i < HID * CIN; i += blockDim.x) sW[i] = W[i];

    int h = threadIdx.x;
    float g_ = isQ ? gq[h] : gk[h];
    float b_ = isQ ? bq[h] : bk[h];
    float m_ = isQ ? mq[h] : mk[h];
    float v_ = isQ ? vq[h] : vk[h];
    float scale = g_ / sqrtf(v_ + 1e-5f);
    float shift = b_ - m_ * scale;

    const float* X = isQ ? cent : feat;
    long rbase = isQ ? row0 : row0 - (long)Bb * Mm;
    __nv_bfloat16* dst = isQ ? g_A : g_Bm;
    __syncthreads();

    for (int r = 0; r < ROWS; r++) {
        long row = rbase + r;
        if (threadIdx.x < CIN) sin[threadIdx.x] = X[row * CIN + threadIdx.x];
        __syncthreads();
        float a0 = 0.0f, a1 = 0.0f;
        #pragma unroll 1
        for (int c = 0; c < CIN - 1; c += 2) {
            a0 = fmaf(sin[c],     sW[h * CIN + c],     a0);
            a1 = fmaf(sin[c + 1], sW[h * CIN + c + 1], a1);
        }
        a0 = fmaf(sin[CIN - 1], sW[h * CIN + CIN - 1], a0);
        float out = (a0 + a1) * scale + shift;
        __nv_bfloat16 hi = __float2bfloat16(out);
        __nv_bfloat16 lo = __float2bfloat16(out - __bfloat162float(hi));
        __nv_bfloat16* d = dst + row * (long)KS;
        if (isQ) { d[h] = hi; d[HID + h] = lo; d[2 * HID + h] = hi; }
        else     { d[h] = hi; d[HID + h] = hi; d[2 * HID + h] = lo; }
        __syncthreads();
    }
}

// ================= K2: 3-stage pipelined mma.sync bf16 GEMM =================
static constexpr int CH    = 64;
static constexpr int NCH   = KS / CH;             // 6
static constexpr int PITCH = CH * 2 + 16;         // 144 B/row
static constexpr int STG_T = 128 * PITCH;         // 18432
static constexpr int STG   = 2 * STG_T;           // 36864
static constexpr int GEMM_SMEM = 3 * STG;         // 110592

__device__ __forceinline__ void ldsm_x4(uint32_t& r0, uint32_t& r1, uint32_t& r2, uint32_t& r3,
                                        uint32_t addr) {
    asm volatile("ldmatrix.sync.aligned.m8n8.x4.shared.b16 {%0,%1,%2,%3}, [%4];"
                 : "=r"(r0), "=r"(r1), "=r"(r2), "=r"(r3) : "r"(addr));
}
__device__ __forceinline__ void mma_16816(float* c, const uint32_t* a, const uint32_t* b) {
    asm volatile("mma.sync.aligned.m16n8k16.row.col.f32.bf16.bf16.f32 "
                 "{%0,%1,%2,%3}, {%4,%5,%6,%7}, {%8,%9}, {%0,%1,%2,%3};"
                 : "+f"(c[0]), "+f"(c[1]), "+f"(c[2]), "+f"(c[3])
                 : "r"(a[0]), "r"(a[1]), "r"(a[2]), "r"(a[3]), "r"(b[0]), "r"(b[1]));
}
__device__ __forceinline__ void cp16(uint32_t saddr, const void* g) {
    asm volatile("cp.async.cg.shared.global [%0], [%1], 16;" :: "r"(saddr), "l"(g));
}

__device__ __forceinline__ void load_stage(const char* gA, const char* gB,
                                           uint32_t stage_base, int tid)
{
    #pragma unroll
    for (int j = 0; j < 4; j++) {
        int i = tid + j * 256;
        int row = i >> 3, seg = i & 7;
        uint32_t so = (uint32_t)(row * PITCH + seg * 16);
        size_t   go = (size_t)row * (KS * 2) + seg * 16;
        cp16(stage_base + so,         gA + go);
        cp16(stage_base + STG_T + so, gB + go);
    }
    asm volatile("cp.async.commit_group;" ::: "memory");
}

__global__ void __launch_bounds__(256, 2) gemm_kernel(float* __restrict__ out)
{
    extern __shared__ char smem[];
    uint32_t sbase = smem_to_u32(smem);
    int tid = threadIdx.x, wid = tid >> 5, lane = tid & 31;
    int nb = blockIdx.x, mb = blockIdx.y, b = blockIdx.z;

    const char* gA = reinterpret_cast<const char*>(g_A)  + (size_t)(b * Mm + mb * 128) * KS * 2;
    const char* gB = reinterpret_cast<const char*>(g_Bm) + (size_t)(b * Nn + nb * 128) * KS * 2;

    load_stage(gA,          gB,          sbase,       tid);
    load_stage(gA + CH * 2, gB + CH * 2, sbase + STG, tid);

    int wm = wid >> 2;
    int wn = wid & 3;
    uint32_t aRowOff = (uint32_t)((wm * 64 + (lane & 15)) * PITCH + ((lane >> 4) * 8) * 2);
    uint32_t bRowOff = (uint32_t)(STG_T + (wn * 32 + (lane & 7) + ((lane >> 4) & 1) * 8) * PITCH
                                  + (((lane >> 3) & 1) * 8) * 2);

    float c[4][4][4];
    #pragma unroll
    for (int i = 0; i < 4; i++)
        #pragma unroll
        for (int j = 0; j < 4; j++)
            #pragma unroll
            for (int r = 0; r < 4; r++) c[i][j][r] = 0.0f;

    int st = 0;
    #pragma unroll 1
    for (int ch = 0; ch < NCH; ch++) {
        if (ch < NCH - 2) asm volatile("cp.async.wait_group 1;" ::: "memory");
        else              asm volatile("cp.async.wait_group 0;" ::: "memory");
        __syncthreads();

        if (ch + 2 < NCH) {
            int nst = st + 2; if (nst >= 3) nst -= 3;
            load_stage(gA + (size_t)(ch + 2) * CH * 2, gB + (size_t)(ch + 2) * CH * 2,
                       sbase + nst * STG, tid);
        }

        uint32_t aB = sbase + st * STG + aRowOff;
        uint32_t bB = sbase + st * STG + bRowOff;

        #pragma unroll
        for (int kk = 0; kk < CH / 16; kk++) {
            uint32_t kOff = (uint32_t)(kk * 32);
            uint32_t a[4][4];
            #pragma unroll
            for (int mi = 0; mi < 4; mi++)
                ldsm_x4(a[mi][0], a[mi][1], a[mi][2], a[mi][3],
                        aB + (uint32_t)(mi * 16 * PITCH) + kOff);
            uint32_t bf[4][2];
            #pragma unroll
            for (int p = 0; p < 2; p++) {
                uint32_t r0, r1, r2, r3;
                ldsm_x4(r0, r1, r2, r3, bB + (uint32_t)(p * 16 * PITCH) + kOff);
                bf[2 * p][0] = r0;     bf[2 * p][1] = r1;
                bf[2 * p + 1][0] = r2; bf[2 * p + 1][1] = r3;
            }
            #pragma unroll
            for (int mi = 0; mi < 4; mi++)
                #pragma unroll
                for (int nj = 0; nj < 4; nj++)
                    mma_16816(c[mi][nj], a[mi], bf[nj]);
        }

        if (++st >= 3) st -= 3;
    }

    int g = lane >> 2, tg = lane & 3;
    long rowBase = (long)(b * Mm + mb * 128 + wm * 64);
    int colBase = nb * 128 + wn * 32 + 2 * tg;
    #pragma unroll
    for (int mi = 0; mi < 4; mi++) {
        #pragma unroll
        for (int nj = 0; nj < 4; nj++) {
            float* p0 = out + (rowBase + mi * 16 + g) * Nn + colBase + nj * 8;
            float* p1 = out + (rowBase + mi * 16 + g + 8) * Nn + colBase + nj * 8;
            *reinterpret_cast<float2*>(p0) = make_float2(c[mi][nj][0], c[mi][nj][1]);
            *reinterpret_cast<float2*>(p1) = make_float2(c[mi][nj][2], c[mi][nj][3]);
        }
    }
}

// ================= block reduce helpers (512 threads = 16 warps) =================
__device__ __forceinline__ float block_sum(float v, float* red)
{
    int tid = threadIdx.x, lid = tid & 31, wid = tid >> 5;
    #pragma unroll
    for (int o = 16; o; o >>= 1) v += __shfl_xor_sync(0xffffffffu, v, o);
    if (lid == 0) red[wid] = v;
    __syncthreads();
    if (wid == 0) {
        float w = (lid < 16) ? red[lid] : 0.0f;
        #pragma unroll
        for (int o = 8; o; o >>= 1) w += __shfl_xor_sync(0xffffffffu, w, o);
        if (lid == 0) red[0] = w;
    }
    __syncthreads();
    float r = red[0];
    __syncthreads();
    return r;
}
__device__ __forceinline__ float block_max(float v, float* red)
{
    int tid = threadIdx.x, lid = tid & 31, wid = tid >> 5;
    #pragma unroll
    for (int o = 16; o; o >>= 1) v = fmaxf(v, __shfl_xor_sync(0xffffffffu, v, o));
    if (lid == 0) red[wid] = v;
    __syncthreads();
    if (wid == 0) {
        float w = (lid < 16) ? red[lid] : -3.0e38f;
        #pragma unroll
        for (int o = 8; o; o >>= 1) w = fmaxf(w, __shfl_xor_sync(0xffffffffu, w, o));
        if (lid == 0) red[0] = w;
    }
    __syncthreads();
    float r = red[0];
    __syncthreads();
    return r;
}

// ================= K3: softmax + sqrt-transform, t -> fp16, col partials =====
// 16 rows per CTA, float4 in, half4 out, next-row prefetch before both reduces.
__global__ void __launch_bounds__(512) softmax_kernel(const float* __restrict__ buf,
                                                      const float* __restrict__ mask)
{
    __shared__ float red[16];
    int mblk = blockIdx.x;          // 0..63
    int b = blockIdx.y;             // 0..15
    int tid = threadIdx.x;
    long row0 = (long)b * Mm + mblk * 16;

    float ca[8];
    #pragma unroll
    for (int j = 0; j < 8; j++) ca[j] = 0.0f;

    float4 x[2], mv[2];
    {
        const float4* xr = reinterpret_cast<const float4*>(buf + row0 * Nn);
        const float4* mr = reinterpret_cast<const float4*>(mask + row0 * Nn);
        x[0] = xr[tid]; x[1] = xr[tid + 512];
        mv[0] = mr[tid]; mv[1] = mr[tid + 512];
    }

    #pragma unroll 1
    for (int r = 0; r < 16; r++) {
        long row = row0 + r;

        float xi[8], mq[8];
        float lmx = -3.0e38f;
        #pragma unroll
        for (int j = 0; j < 2; j++) {
            const float* xp = reinterpret_cast<const float*>(&x[j]);
            const float* mp = reinterpret_cast<const float*>(&mv[j]);
            #pragma unroll
            for (int k = 0; k < 4; k++) {
                float m = mp[k];
                float v = (m < 1e-9f) ? -1e9f : xp[k];
                xi[j * 4 + k] = v;
                mq[j * 4 + k] = m + 1e-9f;
                lmx = fmaxf(lmx, v);
            }
        }

        if (r < 15) {
            const float4* xr = reinterpret_cast<const float4*>(buf + (row + 1) * Nn);
            const float4* mr = reinterpret_cast<const float4*>(mask + (row + 1) * Nn);
            x[0] = xr[tid]; x[1] = xr[tid + 512];
            mv[0] = mr[tid]; mv[1] = mr[tid + 512];
        }

        float rm = block_max(lmx, red);

        float s = 0.0f;
        #pragma unroll
        for (int j = 0; j < 8; j++) { xi[j] = __expf(xi[j] - rm); s += xi[j]; }
        s = block_sum(s, red);
        float inv = 1.0f / s;

        // write t as fp16 (4 halves = uint2 per chunk); accumulate the ROUNDED value
        uint2* tw = reinterpret_cast<uint2*>(g_T + row * Nn);
        #pragma unroll
        for (int j = 0; j < 2; j++) {
            __half h4[4];
            #pragma unroll
            for (int k = 0; k < 4; k++) {
                float p = xi[j * 4 + k] * inv;
                float t = sqrtf(mq[j * 4 + k] * (p + 1e-9f)) - 1e-9f;
                h4[k] = __float2half_rn(t);
                ca[j * 4 + k] += __half2float(h4[k]);
            }
            tw[tid + j * 512] = *reinterpret_cast<uint2*>(h4);
        }
    }

    float4* part = reinterpret_cast<float4*>(g_partial[mblk] + b * Nn);
    #pragma unroll
    for (int j = 0; j < 2; j++) {
        float4 o;
        o.x = ca[j * 4 + 0]; o.y = ca[j * 4 + 1];
        o.z = ca[j * 4 + 2]; o.w = ca[j * 4 + 3];
        part[tid + j * 512] = o;
    }
}

// ================= K3b: finalize column sums =================
__global__ void __launch_bounds__(256) colsum_fin_kernel()
{
    int i = blockIdx.x * 256 + threadIdx.x;
    float s = 0.0f;
    #pragma unroll
    for (int ms = 0; ms < Mm / 16; ms++) s += g_partial[ms][i];
    g_rcolsum[i] = 1.0f / fmaxf(s, 1e-12f);
}

// ================= K4: column norm + row norm (half t in, fp32 out) =================
__global__ void __launch_bounds__(512) norm_kernel(float* __restrict__ out)
{
    __shared__ float red[16];
    long row = blockIdx.x;
    int b = (int)(row >> 10);
    const uint2* tr = reinterpret_cast<const uint2*>(g_T + row * Nn);
    const float4* rc = reinterpret_cast<const float4*>(g_rcolsum + b * Nn);
    float4* ow = reinterpret_cast<float4*>(out + row * Nn);
    int tid = threadIdx.x;

    float u[2][4];
    float s = 0.0f;
    #pragma unroll
    for (int j = 0; j < 2; j++) {
        uint2 tv = tr[tid + j * 512];
        const __half* hp = reinterpret_cast<const __half*>(&tv);
        float4 r = rc[tid + j * 512];
        u[j][0] = __half2float(hp[0]) * r.x;
        u[j][1] = __half2float(hp[1]) * r.y;
        u[j][2] = __half2float(hp[2]) * r.z;
        u[j][3] = __half2float(hp[3]) * r.w;
        s += u[j][0] + u[j][1] + u[j][2] + u[j][3];
    }
    s = block_sum(s, red);
    float inv = 1.0f / fmaxf(s, 1e-12f);
    #pragma unroll
    for (int j = 0; j < 2; j++) {
        float4 o;
        o.x = u[j][0] * inv; o.y = u[j][1] * inv;
        o.z = u[j][2] * inv; o.w = u[j][3] * inv;
        ow[tid + j * 512] = o;
    }
}

// ================= launch =================
extern "C" void kernel_launch(void* const* d_in, const int* in_sizes, int n_in,
                              void* d_out, int out_size)
{
    const float* cent = (const float*)d_in[0];
    const float* feat = (const float*)d_in[1];
    const float* mask = (const float*)d_in[2];
    const float* Wq = (const float*)d_in[3];
    const float* Wk = (const float*)d_in[4];
    const float* gq = (const float*)d_in[5];
    const float* bq = (const float*)d_in[6];
    const float* mq = (const float*)d_in[7];
    const float* vq = (const float*)d_in[8];
    const float* gk = (const float*)d_in[9];
    const float* bk = (const float*)d_in[10];
    const float* mk = (const float*)d_in[11];
    const float* vk = (const float*)d_in[12];
    float* out = (float*)d_out;

    qk_kernel<<<(Bb * Mm + Bb * Nn) / 64, 128>>>(cent, feat, Wq, Wk,
                                                 gq, bq, mq, vq, gk, bk, mk, vk);

    cudaFuncSetAttribute(gemm_kernel, cudaFuncAttributeMaxDynamicSharedMemorySize, GEMM_SMEM);
    gemm_kernel<<<dim3(Nn / 128, Mm / 128, Bb), 256, GEMM_SMEM>>>(out);

    softmax_kernel<<<dim3(Mm / 16, Bb), 512>>>(out, mask);

    colsum_fin_kernel<<<(Bb * Nn) / 256, 256>>>();

    norm_kernel<<<Bb * Mm, 512>>>(out);
}